// round 14
// baseline (speedup 1.0000x reference)
#include <cuda_runtime.h>
#include <cuda_fp16.h>
#include <cstdint>

// Problem dims (fixed by reference)
#define T_DIM 1024
#define B_DIM 32
#define K_DIM 8
#define N_DIM 64
#define M_DIM 64
#define KN    512      // K_DIM * N_DIM
#define BK    256      // B_DIM * K_DIM
#define ROWS  32768    // T*B rows of the big GEMM
#define KTOT  1024     // real K (re|im interleaved pairs; 512 uint32 per row)
#define NTOT  128      // output cols (re|im stacked)

#define X_SZ   (T_DIM * B_DIM * K_DIM)   // 262144
#define C_SZ   (K_DIM * N_DIM * M_DIM)   // 32768
#define V_SZ   (K_DIM * N_DIM)           // 512
#define OUT_CPLX (T_DIM * B_DIM * M_DIM) // 2097152 complex values

// A scaled by 1/16, B scaled by 16 (cancels exactly in the product).
#define A_SCALE 0.0625f
#define B_SCALE 16.0f

// ---------------- scratch (static device allocations only) ----------------
__device__ uint32_t g_Ah[(size_t)ROWS * 512];    // 64 MiB, packed f16x2 (re,im)
__device__ uint32_t g_Bh[NTOT * 512];            // 256 KiB, [n][kk] K-major packed f16x2

// ---------------- PTX helpers (base sm_100 features only) ----------------
__device__ __forceinline__ uint32_t smem_u32(const void* p) {
    uint32_t a;
    asm("{ .reg .u64 t; cvta.to.shared.u64 t, %1; cvt.u32.u64 %0, t; }" : "=r"(a) : "l"(p));
    return a;
}
__device__ __forceinline__ void ldsm_x4(uint32_t* r, uint32_t addr) {
    asm volatile("ldmatrix.sync.aligned.m8n8.x4.shared.b16 {%0,%1,%2,%3}, [%4];"
                 : "=r"(r[0]), "=r"(r[1]), "=r"(r[2]), "=r"(r[3]) : "r"(addr));
}
__device__ __forceinline__ void mma_f16(float* d, const uint32_t* a, const uint32_t* b) {
    asm volatile("mma.sync.aligned.m16n8k16.row.col.f32.f16.f16.f32 "
                 "{%0,%1,%2,%3}, {%4,%5,%6,%7}, {%8,%9}, {%0,%1,%2,%3};"
                 : "+f"(d[0]), "+f"(d[1]), "+f"(d[2]), "+f"(d[3])
                 : "r"(a[0]), "r"(a[1]), "r"(a[2]), "r"(a[3]), "r"(b[0]), "r"(b[1]));
}
#define CP16(dst, src) \
    asm volatile("cp.async.cg.shared.global [%0], [%1], 16;" :: "r"(dst), "l"(src))
#define CP_COMMIT() asm volatile("cp.async.commit_group;" ::: "memory")
#define CP_WAIT(n)  asm volatile("cp.async.wait_group %0;" :: "n"(n) : "memory")

__device__ __forceinline__ uint32_t pack_f16x2(float lo, float hi) {
    __half2 h = __floats2half2_rn(lo, hi);   // lo -> low 16, hi -> high 16
    return *(uint32_t*)&h;
}

// ---------------- kernel A: fused prep + scan -----------------------------
// blocks 0..255: per-(b,k) scan; each block computes its own B' slice inline.
// blocks 256..287: bprep (stacked fp16 B operand), independent of B'.
__global__ __launch_bounds__(64) void prep_scan_kernel(
        const float* __restrict__ x,
        const float* __restrict__ lam_re,
        const float* __restrict__ lam_im,
        const float* __restrict__ C_re,
        const float* __restrict__ C_im) {
    int tid = threadIdx.x;

    if (blockIdx.x >= 256) {
        // ---- bprep: B[n][2p] / B[n][2p+1] stacked, x16 scaled fp16 ----
        int base = (blockIdx.x - 256) * 64 + tid;     // 2048 threads
        #pragma unroll 4
        for (int id = base; id < NTOT * 512; id += 2048) {
            int n = id >> 9;
            int p = id & 511;
            int m = n & 63;
            float v0, v1;
            if (n < 64) { v0 = C_re[p * 64 + m]; v1 = -C_im[p * 64 + m]; }
            else        { v0 = C_im[p * 64 + m]; v1 =  C_re[p * 64 + m]; }
            g_Bh[id] = pack_f16x2(v0 * B_SCALE, v1 * B_SCALE);
        }
        return;
    }

    // ---- scan block for (b, k) ----
    int bk = blockIdx.x;
    int b = bk >> 3;
    int k = bk & 7;
    int n = tid;                       // 0..63
    int kn = (k << 6) | n;

    __shared__ float lamr[64], lami[64];
    __shared__ float xs[64];
    lamr[n] = lam_re[kn];
    lami[n] = lam_im[kn];
    __syncthreads();

    float lr = lamr[n], li = lami[n];

    // inline B'[k,n] = exp(-sum_{i!=n} log(1 - lam_i/lam_n))
    float den = lr * lr + li * li;
    float sr = 0.f, si = 0.f;
    #pragma unroll 8
    for (int i = 0; i < 64; ++i) {
        if (i == n) continue;
        float lir = lamr[i], lii = lami[i];
        float rr = (lir * lr + lii * li) / den;
        float ri = (lii * lr - lir * li) / den;
        float wr = 1.f - rr, wi = -ri;
        sr += 0.5f * logf(wr * wr + wi * wi);
        si += atan2f(wi, wr);
    }
    float er = expf(-sr);
    float sn, cs; sincosf(si, &sn, &cs);
    float2 Bp = make_float2(er * cs, -er * sn);

    float2 s1 = make_float2(0.f, 0.f);
    float2 s2 = make_float2(0.f, 0.f);
    float2 s3 = make_float2(0.f, 0.f);
    float p1r = 0.f, p1i = 0.f, p2r = 0.f, p2i = 0.f, p3r = 0.f, p3i = 0.f;
    float a1c = 1.f, a2c = 1.f;

    const int xoff = b * K_DIM + k;

    for (int tt = 0; tt < T_DIM; tt += 64) {
        __syncthreads();
        int tl = tt + n;
        xs[n] = (tl == 0) ? 0.f : x[(tl - 1) * BK + xoff];
        __syncthreads();
        #pragma unroll 8
        for (int j = 0; j < 64; ++j) {
            float xm1 = xs[j];
            float bxr = Bp.x * xm1, bxi = Bp.y * xm1;
            // state updates use CARRIED p (= lam*s_{t-1}) and alphas
            s3.x = fmaf(a2c, p3r, bxr);  s3.y = fmaf(a2c, p3i, bxi);
            s2.x = fmaf(a1c, p2r, bxr);  s2.y = fmaf(a1c, p2i, bxi);
            s1.x = p1r + bxr;            s1.y = p1i + bxi;
            // prepare next-step products and alphas (off critical path)
            p1r = lr * s1.x - li * s1.y;  p1i = lr * s1.y + li * s1.x;
            p2r = lr * s2.x - li * s2.y;  p2i = lr * s2.y + li * s2.x;
            p3r = lr * s3.x - li * s3.y;  p3i = lr * s3.y + li * s3.x;
            a1c = rsqrtf(1.f + p1r * p1r + p1i * p1i);
            a2c = rsqrtf(1.f + p2r * p2r + p2i * p2i);
            // emit fp16 (scaled by 1/16)
            uint32_t ro = (((tt + j) << 5) + b) * 512 + kn;
            g_Ah[ro] = pack_f16x2(s3.x * A_SCALE, s3.y * A_SCALE);
        }
    }
}

// ---------------- kernel B: mma.sync f16 GEMM, k64 chunks, 3-stage --------
// CTA 512 thr (16 warps, 8m x 2n), tile 256x128, warp tile 32x64.
// 16 chunks of k64 -> 16 barriers. Per chunk: CP_WAIT -> __syncthreads ->
// issue kc+2 -> compute kc (R7/R13-proven ordering; R8-verified addressing).
#define SROW 144                           // 128B data + 16B pad, 16B aligned
#define AH_OFF 0
#define BH_OFF (256 * SROW)                // 36864
#define STAGE_BYTES (BH_OFF + 128 * SROW)  // 55296
#define NSTAGE 3
#define NCHUNK 16

extern __shared__ uint8_t dynSmem[];

__device__ __forceinline__ void issue_chunk(int kc, uint32_t sbuf, int rowBase,
                                            int tid) {
    int k0b = kc * 128;   // byte offset of k64 chunk within a 2048B row
    const uint8_t* gAh = (const uint8_t*)g_Ah;
    const uint8_t* gBh = (const uint8_t*)g_Bh;
    // A: 256 rows x 128B; thread -> (row = tid>>1, half = tid&1), 4x16B
    {
        int row = tid >> 1, half = tid & 1;
        size_t ga = (size_t)(rowBase + row) * 2048 + k0b + half * 64;
        uint32_t so = sbuf + AH_OFF + row * SROW + half * 64;
        #pragma unroll
        for (int i = 0; i < 4; ++i) CP16(so + i * 16, gAh + ga + i * 16);
    }
    // B: 128 rows x 128B; thread -> (row = tid>>2, q = tid&3), 2x16B
    {
        int row = tid >> 2, q = tid & 3;
        size_t gb = (size_t)row * 2048 + k0b + q * 32;
        uint32_t so = sbuf + BH_OFF + row * SROW + q * 32;
        #pragma unroll
        for (int i = 0; i < 2; ++i) CP16(so + i * 16, gBh + gb + i * 16);
    }
}

__global__ __launch_bounds__(512, 1) void gemm_mma(
        const float* __restrict__ x, const float* __restrict__ D,
        const float* __restrict__ Do, float* __restrict__ out, int writeCplx) {
    __shared__ float Ds[512];
    __shared__ float doSum[64];

    int tid = threadIdx.x;
    int wid = tid >> 5, lane = tid & 31;
    int wm = wid & 7, wn = wid >> 3;          // warp grid 8m x 2n
    int rowBase = blockIdx.x * 256;

    Ds[tid] = D[tid];
    if (tid < 64) {
        float s = 0.f;
        #pragma unroll
        for (int k = 0; k < K_DIM; ++k) s += Do[k * 64 + tid];
        doSum[tid] = s;
    }

    uint32_t sbase0 = smem_u32(dynSmem);

    // ldmatrix per-thread address components
    int mi = lane >> 3;                        // 0..3
    int arow = (lane & 7) + (mi & 1) * 8;
    int acol16 = mi >> 1;
    int bnrow = (mi >> 1) * 8 + (lane & 7);
    int bk16 = mi & 1;

    float acc[2][8][4];
    #pragma unroll
    for (int mt = 0; mt < 2; ++mt)
        #pragma unroll
        for (int nt = 0; nt < 8; ++nt)
            #pragma unroll
            for (int e = 0; e < 4; ++e) acc[mt][nt][e] = 0.f;

    issue_chunk(0, sbase0, rowBase, tid);
    CP_COMMIT();
    issue_chunk(1, sbase0 + STAGE_BYTES, rowBase, tid);
    CP_COMMIT();

    int buf = 0;                               // buffer index of chunk kc
    #pragma unroll 1
    for (int kc = 0; kc < NCHUNK; ++kc) {
        if (kc + 1 < NCHUNK) { CP_WAIT(1); } else { CP_WAIT(0); }
        __syncthreads();   // all threads: chunk kc landed; compute(kc-1) done
        if (kc + 2 < NCHUNK) {
            int nb = buf + 2; if (nb >= NSTAGE) nb -= NSTAGE;
            issue_chunk(kc + 2, sbase0 + nb * STAGE_BYTES, rowBase, tid);
            CP_COMMIT();
        }

        uint32_t sAh = sbase0 + buf * STAGE_BYTES;
        uint32_t sBh = sAh + BH_OFF;

        #pragma unroll
        for (int ks = 0; ks < 4; ++ks) {
            uint32_t ah[2][4];
            #pragma unroll
            for (int mt = 0; mt < 2; ++mt) {
                uint32_t off = (wm * 32 + mt * 16 + arow) * SROW + ks * 32 + acol16 * 16;
                ldsm_x4(ah[mt], sAh + off);
            }
            #pragma unroll
            for (int ntp = 0; ntp < 4; ++ntp) {
                uint32_t boff = (wn * 64 + ntp * 16 + bnrow) * SROW + ks * 32 + bk16 * 16;
                uint32_t bh4[4];
                ldsm_x4(bh4, sBh + boff);
                #pragma unroll
                for (int mt = 0; mt < 2; ++mt) {
                    mma_f16(acc[mt][2 * ntp],     ah[mt], bh4);
                    mma_f16(acc[mt][2 * ntp + 1], ah[mt], bh4 + 2);
                }
            }
        }
        ++buf; if (buf >= NSTAGE) buf = 0;
    }

    // epilogue (A_SCALE * B_SCALE = 1 -> no extra factor)
    int gID = lane >> 2, tg = lane & 3;
    #pragma unroll
    for (int mt = 0; mt < 2; ++mt) {
        #pragma unroll
        for (int half = 0; half < 2; ++half) {
            int R = rowBase + wm * 32 + mt * 16 + gID + half * 8;
            float xv[K_DIM];
            #pragma unroll
            for (int k = 0; k < K_DIM; ++k) xv[k] = x[R * K_DIM + k];
            #pragma unroll
            for (int nt = 0; nt < 8; ++nt) {
                #pragma unroll
                for (int e = 0; e < 2; ++e) {
                    int col = wn * 64 + nt * 8 + tg * 2 + e;
                    float a = acc[mt][nt][half * 2 + e];
                    if (wn == 0) {  // real part: add x*D + Do, scale by 1/8
                        int m = col;
                        float dt = doSum[m];
                        #pragma unroll
                        for (int k = 0; k < K_DIM; ++k)
                            dt = fmaf(xv[k], Ds[k * 64 + m], dt);
                        float v = (a + dt) * 0.125f;
                        if (writeCplx) out[((size_t)R * 64 + m) * 2] = v;
                        else           out[(size_t)R * 64 + m] = v;
                    } else {        // imag part
                        int m = col - 64;
                        if (writeCplx) out[((size_t)R * 64 + m) * 2 + 1] = a * 0.125f;
                    }
                }
            }
        }
    }
}

// ---------------- launch ----------------
extern "C" void kernel_launch(void* const* d_in, const int* in_sizes, int n_in,
                              void* d_out, int out_size) {
    const float* x = nullptr;
    const float* cbuf[2] = {nullptr, nullptr};
    const float* vbuf[4] = {nullptr, nullptr, nullptr, nullptr};
    int nc = 0, nv = 0;
    for (int i = 0; i < n_in; ++i) {
        int sz = in_sizes[i];
        const float* p = (const float*)d_in[i];
        if (sz == X_SZ) x = p;
        else if (sz == C_SZ) { if (nc < 2) cbuf[nc++] = p; }
        else if (sz == V_SZ) { if (nv < 4) vbuf[nv++] = p; }
    }
    if (!x || nc < 2 || nv < 4) return;
    const float* C_re   = cbuf[0];
    const float* C_im   = cbuf[1];
    const float* lam_re = vbuf[0];
    const float* lam_im = vbuf[1];
    const float* D      = vbuf[2];
    const float* Do     = vbuf[3];

    int writeCplx = (out_size >= 2 * OUT_CPLX) ? 1 : 0;

    cudaFuncSetAttribute(gemm_mma, cudaFuncAttributeMaxDynamicSharedMemorySize,
                         NSTAGE * STAGE_BYTES);

    prep_scan_kernel<<<288, 64>>>(x, lam_re, lam_im, C_re, C_im);
    gemm_mma<<<ROWS / 256, 512, NSTAGE * STAGE_BYTES>>>(x, D, Do, (float*)d_out, writeCplx);
}

// round 15
// speedup vs baseline: 1.1235x; 1.1235x over previous
#include <cuda_runtime.h>
#include <cuda_fp16.h>
#include <cstdint>

// Problem dims (fixed by reference)
#define T_DIM 1024
#define B_DIM 32
#define K_DIM 8
#define N_DIM 64
#define M_DIM 64
#define KN    512      // K_DIM * N_DIM
#define BK    256      // B_DIM * K_DIM
#define ROWS  32768    // T*B rows of the big GEMM
#define KTOT  1024     // real K (re|im interleaved pairs; 512 uint32 per row)
#define NTOT  128      // output cols (re|im stacked)

#define X_SZ   (T_DIM * B_DIM * K_DIM)   // 262144
#define C_SZ   (K_DIM * N_DIM * M_DIM)   // 32768
#define V_SZ   (K_DIM * N_DIM)           // 512
#define OUT_CPLX (T_DIM * B_DIM * M_DIM) // 2097152 complex values

// A scaled by 1/16, B scaled by 16 (cancels exactly in the product).
#define A_SCALE 0.0625f
#define B_SCALE 16.0f

// ---------------- scratch (static device allocations only) ----------------
__device__ float2   g_Bp[KN];
__device__ uint32_t g_Ah[(size_t)ROWS * 512];    // 64 MiB, packed f16x2 (re,im)
__device__ uint32_t g_Bh[NTOT * 512];            // 256 KiB, [n][kk] K-major packed f16x2

// ---------------- PTX helpers (base sm_100 features only) ----------------
__device__ __forceinline__ uint32_t smem_u32(const void* p) {
    uint32_t a;
    asm("{ .reg .u64 t; cvta.to.shared.u64 t, %1; cvt.u32.u64 %0, t; }" : "=r"(a) : "l"(p));
    return a;
}
__device__ __forceinline__ void ldsm_x4(uint32_t* r, uint32_t addr) {
    asm volatile("ldmatrix.sync.aligned.m8n8.x4.shared.b16 {%0,%1,%2,%3}, [%4];"
                 : "=r"(r[0]), "=r"(r[1]), "=r"(r[2]), "=r"(r[3]) : "r"(addr));
}
__device__ __forceinline__ void mma_f16(float* d, const uint32_t* a, const uint32_t* b) {
    asm volatile("mma.sync.aligned.m16n8k16.row.col.f32.f16.f16.f32 "
                 "{%0,%1,%2,%3}, {%4,%5,%6,%7}, {%8,%9}, {%0,%1,%2,%3};"
                 : "+f"(d[0]), "+f"(d[1]), "+f"(d[2]), "+f"(d[3])
                 : "r"(a[0]), "r"(a[1]), "r"(a[2]), "r"(a[3]), "r"(b[0]), "r"(b[1]));
}
#define CP16(dst, src) \
    asm volatile("cp.async.cg.shared.global [%0], [%1], 16;" :: "r"(dst), "l"(src))
#define CP_COMMIT() asm volatile("cp.async.commit_group;" ::: "memory")
#define CP_WAIT(n)  asm volatile("cp.async.wait_group %0;" :: "n"(n) : "memory")

__device__ __forceinline__ uint32_t pack_f16x2(float lo, float hi) {
    __half2 h = __floats2half2_rn(lo, hi);   // lo -> low 16, hi -> high 16
    return *(uint32_t*)&h;
}

// ---------------- kernel 1: merged B' + B-operand prep --------------------
// blocks 0..511: bp (one (k,j) mode each, 64-way parallel reduce)
// blocks 512..575: bprep (stacked fp16 B operand; 4096 threads, 16 ids each)
__global__ void prep_kernel(const float* __restrict__ lam_re,
                            const float* __restrict__ lam_im,
                            const float* __restrict__ C_re,
                            const float* __restrict__ C_im) {
    int i = threadIdx.x;

    if (blockIdx.x >= 512) {
        int base = (blockIdx.x - 512) * 64 + i;     // 4096 threads
        #pragma unroll 4
        for (int id = base; id < NTOT * 512; id += 4096) {
            int n = id >> 9;
            int p = id & 511;
            int m = n & 63;
            float v0, v1;
            if (n < 64) { v0 = C_re[p * 64 + m]; v1 = -C_im[p * 64 + m]; }
            else        { v0 = C_im[p * 64 + m]; v1 =  C_re[p * 64 + m]; }
            g_Bh[id] = pack_f16x2(v0 * B_SCALE, v1 * B_SCALE);
        }
        return;
    }

    __shared__ float ssr[64], ssi[64];
    int idx = blockIdx.x;
    int j = idx & 63;
    int base = idx & ~63;
    float sr = 0.f, si = 0.f;
    if (i != j) {
        float ljr = lam_re[idx], lji = lam_im[idx];
        float den = ljr * ljr + lji * lji;
        float lir = lam_re[base + i], lii = lam_im[base + i];
        float rr = (lir * ljr + lii * lji) / den;
        float ri = (lii * ljr - lir * lji) / den;
        float wr = 1.f - rr, wi = -ri;
        sr = 0.5f * logf(wr * wr + wi * wi);
        si = atan2f(wi, wr);
    }
    ssr[i] = sr; ssi[i] = si;
    __syncthreads();
    #pragma unroll
    for (int s = 32; s > 0; s >>= 1) {
        if (i < s) { ssr[i] += ssr[i + s]; ssi[i] += ssi[i + s]; }
        __syncthreads();
    }
    if (i == 0) {
        float er = expf(-ssr[0]);
        float sn, cs; sincosf(ssi[0], &sn, &cs);
        g_Bp[idx] = make_float2(er * cs, -er * sn);
    }
}

// ---------------- kernel 2: fused 3-pass scan, fp16 output ----------------
// 128 threads = 4 warps per block (uses ALL 4 SMSPs; 64-thread blocks only
// ever occupied SMSP 0/1 via wid%4). Block handles TWO (b,k) chains:
// bk2 = blockIdx.x in 0..127: b = bk2>>2, k = (bk2&3)*2 + (tid>>6), n = tid&63.
__global__ __launch_bounds__(128) void scan_kernel(
        const float* __restrict__ x,
        const float* __restrict__ lam_re,
        const float* __restrict__ lam_im) {
    int tid = threadIdx.x;
    int b = blockIdx.x >> 2;
    int k = ((blockIdx.x & 3) << 1) + (tid >> 6);
    int n = tid & 63;
    int kn = (k << 6) | n;

    float lr = lam_re[kn], li = lam_im[kn];
    float2 Bp = g_Bp[kn];
    float2 s1 = make_float2(0.f, 0.f);
    float2 s2 = make_float2(0.f, 0.f);
    float2 s3 = make_float2(0.f, 0.f);
    float p1r = 0.f, p1i = 0.f, p2r = 0.f, p2i = 0.f, p3r = 0.f, p3i = 0.f;
    float a1c = 1.f, a2c = 1.f;

    __shared__ float xs[128];
    const int xoff = b * K_DIM + k;
    float* xsh = xs + (tid & 64);      // this chain's 64-entry staging slice

    for (int tt = 0; tt < T_DIM; tt += 64) {
        __syncthreads();
        int tl = tt + n;
        xsh[n] = (tl == 0) ? 0.f : x[(tl - 1) * BK + xoff];
        __syncthreads();
        #pragma unroll 8
        for (int j = 0; j < 64; ++j) {
            float xm1 = xsh[j];
            float bxr = Bp.x * xm1, bxi = Bp.y * xm1;
            // state updates use CARRIED p (= lam*s_{t-1}) and alphas
            s3.x = fmaf(a2c, p3r, bxr);  s3.y = fmaf(a2c, p3i, bxi);
            s2.x = fmaf(a1c, p2r, bxr);  s2.y = fmaf(a1c, p2i, bxi);
            s1.x = p1r + bxr;            s1.y = p1i + bxi;
            // prepare next-step products and alphas (off critical path)
            p1r = lr * s1.x - li * s1.y;  p1i = lr * s1.y + li * s1.x;
            p2r = lr * s2.x - li * s2.y;  p2i = lr * s2.y + li * s2.x;
            p3r = lr * s3.x - li * s3.y;  p3i = lr * s3.y + li * s3.x;
            a1c = rsqrtf(1.f + p1r * p1r + p1i * p1i);
            a2c = rsqrtf(1.f + p2r * p2r + p2i * p2i);
            // emit fp16 (scaled by 1/16)
            uint32_t ro = (((tt + j) << 5) + b) * 512 + kn;
            g_Ah[ro] = pack_f16x2(s3.x * A_SCALE, s3.y * A_SCALE);
        }
    }
}

// ---------------- kernel 3: mma.sync f16 GEMM, single pass, 3-stage -------
// CTA 512 thr (16 warps, 8m x 2n), tile 256x128, warp tile 32x64.
// acc += A*B per 32-wide k chunk (single fp16 pass).
// Per chunk: CP_WAIT -> __syncthreads -> issue kc+2 -> compute kc (R13-proven).
#define SROW 80
#define AH_OFF 0
#define BH_OFF (256 * SROW)               // 20480
#define STAGE_BYTES (BH_OFF + 128 * SROW) // 30720
#define NSTAGE 3
#define NCHUNK 32

extern __shared__ uint8_t dynSmem[];

__device__ __forceinline__ void issue_chunk(int kc, uint32_t sbuf, int rowBase,
                                            int grow, int gc) {
    int k0b = kc * 64;   // byte offset of k32 chunk within a 2048B row
    const uint8_t* gAh = (const uint8_t*)g_Ah;
    const uint8_t* gBh = (const uint8_t*)g_Bh;
    #pragma unroll
    for (int i = 0; i < 2; ++i) {
        int row = grow + i * 128;
        size_t ga = (size_t)(rowBase + row) * (KTOT * 2) + k0b + gc * 16;
        uint32_t so = row * SROW + gc * 16;
        CP16(sbuf + AH_OFF + so, gAh + ga);
    }
    {
        size_t gb = (size_t)grow * (KTOT * 2) + k0b + gc * 16;
        uint32_t so = grow * SROW + gc * 16;
        CP16(sbuf + BH_OFF + so, gBh + gb);
    }
}

__global__ __launch_bounds__(512, 1) void gemm_mma(
        const float* __restrict__ x, const float* __restrict__ D,
        const float* __restrict__ Do, float* __restrict__ out, int writeCplx) {
    __shared__ float Ds[512];
    __shared__ float doSum[64];

    int tid = threadIdx.x;
    int wid = tid >> 5, lane = tid & 31;
    int wm = wid & 7, wn = wid >> 3;          // warp grid 8m x 2n
    int rowBase = blockIdx.x * 256;

    Ds[tid] = D[tid];
    if (tid < 64) {
        float s = 0.f;
        #pragma unroll
        for (int k = 0; k < K_DIM; ++k) s += Do[k * 64 + tid];
        doSum[tid] = s;
    }

    uint32_t sbase0 = smem_u32(dynSmem);

    // ldmatrix per-thread address components
    int mi = lane >> 3;                        // 0..3
    int arow = (lane & 7) + (mi & 1) * 8;
    int acol16 = mi >> 1;
    int bnrow = (mi >> 1) * 8 + (lane & 7);
    int bk16 = mi & 1;

    float acc[2][8][4];
    #pragma unroll
    for (int mt = 0; mt < 2; ++mt)
        #pragma unroll
        for (int nt = 0; nt < 8; ++nt)
            #pragma unroll
            for (int e = 0; e < 4; ++e) acc[mt][nt][e] = 0.f;

    int grow = tid >> 2, gc = tid & 3;         // grow 0..127

    issue_chunk(0, sbase0, rowBase, grow, gc);
    CP_COMMIT();
    issue_chunk(1, sbase0 + STAGE_BYTES, rowBase, grow, gc);
    CP_COMMIT();

    int buf = 0;                               // buffer index of chunk kc
    #pragma unroll 1
    for (int kc = 0; kc < NCHUNK; ++kc) {
        if (kc + 1 < NCHUNK) { CP_WAIT(1); } else { CP_WAIT(0); }
        __syncthreads();   // all threads: chunk kc landed; compute(kc-1) done
        if (kc + 2 < NCHUNK) {
            int nb = buf + 2; if (nb >= NSTAGE) nb -= NSTAGE;
            issue_chunk(kc + 2, sbase0 + nb * STAGE_BYTES, rowBase, grow, gc);
            CP_COMMIT();
        }

        uint32_t sAh = sbase0 + buf * STAGE_BYTES;
        uint32_t sBh = sAh + BH_OFF;

        #pragma unroll
        for (int ks = 0; ks < 2; ++ks) {
            uint32_t ah[2][4];
            #pragma unroll
            for (int mt = 0; mt < 2; ++mt) {
                uint32_t off = (wm * 32 + mt * 16 + arow) * SROW + ks * 32 + acol16 * 16;
                ldsm_x4(ah[mt], sAh + off);
            }
            #pragma unroll
            for (int ntp = 0; ntp < 4; ++ntp) {
                uint32_t boff = (wn * 64 + ntp * 16 + bnrow) * SROW + ks * 32 + bk16 * 16;
                uint32_t bh4[4];
                ldsm_x4(bh4, sBh + boff);
                #pragma unroll
                for (int mt = 0; mt < 2; ++mt) {
                    mma_f16(acc[mt][2 * ntp],     ah[mt], bh4);
                    mma_f16(acc[mt][2 * ntp + 1], ah[mt], bh4 + 2);
                }
            }
        }
        ++buf; if (buf >= NSTAGE) buf = 0;
    }

    // epilogue (A_SCALE * B_SCALE = 1 -> no extra factor)
    int gID = lane >> 2, tg = lane & 3;
    #pragma unroll
    for (int mt = 0; mt < 2; ++mt) {
        #pragma unroll
        for (int half = 0; half < 2; ++half) {
            int R = rowBase + wm * 32 + mt * 16 + gID + half * 8;
            float xv[K_DIM];
            #pragma unroll
            for (int k = 0; k < K_DIM; ++k) xv[k] = x[R * K_DIM + k];
            #pragma unroll
            for (int nt = 0; nt < 8; ++nt) {
                #pragma unroll
                for (int e = 0; e < 2; ++e) {
                    int col = wn * 64 + nt * 8 + tg * 2 + e;
                    float a = acc[mt][nt][half * 2 + e];
                    if (wn == 0) {  // real part: add x*D + Do, scale by 1/8
                        int m = col;
                        float dt = doSum[m];
                        #pragma unroll
                        for (int k = 0; k < K_DIM; ++k)
                            dt = fmaf(xv[k], Ds[k * 64 + m], dt);
                        float v = (a + dt) * 0.125f;
                        if (writeCplx) out[((size_t)R * 64 + m) * 2] = v;
                        else           out[(size_t)R * 64 + m] = v;
                    } else {        // imag part
                        int m = col - 64;
                        if (writeCplx) out[((size_t)R * 64 + m) * 2 + 1] = a * 0.125f;
                    }
                }
            }
        }
    }
}

// ---------------- launch ----------------
extern "C" void kernel_launch(void* const* d_in, const int* in_sizes, int n_in,
                              void* d_out, int out_size) {
    const float* x = nullptr;
    const float* cbuf[2] = {nullptr, nullptr};
    const float* vbuf[4] = {nullptr, nullptr, nullptr, nullptr};
    int nc = 0, nv = 0;
    for (int i = 0; i < n_in; ++i) {
        int sz = in_sizes[i];
        const float* p = (const float*)d_in[i];
        if (sz == X_SZ) x = p;
        else if (sz == C_SZ) { if (nc < 2) cbuf[nc++] = p; }
        else if (sz == V_SZ) { if (nv < 4) vbuf[nv++] = p; }
    }
    if (!x || nc < 2 || nv < 4) return;
    const float* C_re   = cbuf[0];
    const float* C_im   = cbuf[1];
    const float* lam_re = vbuf[0];
    const float* lam_im = vbuf[1];
    const float* D      = vbuf[2];
    const float* Do     = vbuf[3];

    int writeCplx = (out_size >= 2 * OUT_CPLX) ? 1 : 0;

    cudaFuncSetAttribute(gemm_mma, cudaFuncAttributeMaxDynamicSharedMemorySize,
                         NSTAGE * STAGE_BYTES);

    prep_kernel<<<576, 64>>>(lam_re, lam_im, C_re, C_im);
    scan_kernel<<<128, 128>>>(x, lam_re, lam_im);
    gemm_mma<<<ROWS / 256, 512, NSTAGE * STAGE_BYTES>>>(x, D, Do, (float*)d_out, writeCplx);
}

// round 16
// speedup vs baseline: 1.1413x; 1.0159x over previous
#include <cuda_runtime.h>
#include <cuda_fp16.h>
#include <cstdint>

// Problem dims (fixed by reference)
#define T_DIM 1024
#define B_DIM 32
#define K_DIM 8
#define N_DIM 64
#define M_DIM 64
#define KN    512      // K_DIM * N_DIM
#define BK    256      // B_DIM * K_DIM
#define ROWS  32768    // T*B rows of the big GEMM
#define KTOT  1024     // real K (re|im interleaved pairs; 512 uint32 per row)
#define NTOT  128      // output cols (re|im stacked)

#define X_SZ   (T_DIM * B_DIM * K_DIM)   // 262144
#define C_SZ   (K_DIM * N_DIM * M_DIM)   // 32768
#define V_SZ   (K_DIM * N_DIM)           // 512
#define OUT_CPLX (T_DIM * B_DIM * M_DIM) // 2097152 complex values

// A scaled by 1/16, B scaled by 16 (cancels exactly in the product).
#define A_SCALE 0.0625f
#define B_SCALE 16.0f

// ---------------- scratch (static device allocations only) ----------------
__device__ float2   g_Bp[KN];
__device__ uint32_t g_Ah[(size_t)ROWS * 512];    // 64 MiB, packed f16x2 (re,im)
__device__ uint32_t g_Bh[NTOT * 512];            // 256 KiB, [n][kk] K-major packed f16x2

// ---------------- PTX helpers (base sm_100 features only) ----------------
__device__ __forceinline__ uint32_t smem_u32(const void* p) {
    uint32_t a;
    asm("{ .reg .u64 t; cvta.to.shared.u64 t, %1; cvt.u32.u64 %0, t; }" : "=r"(a) : "l"(p));
    return a;
}
__device__ __forceinline__ void ldsm_x4(uint32_t* r, uint32_t addr) {
    asm volatile("ldmatrix.sync.aligned.m8n8.x4.shared.b16 {%0,%1,%2,%3}, [%4];"
                 : "=r"(r[0]), "=r"(r[1]), "=r"(r[2]), "=r"(r[3]) : "r"(addr));
}
__device__ __forceinline__ void mma_f16(float* d, const uint32_t* a, const uint32_t* b) {
    asm volatile("mma.sync.aligned.m16n8k16.row.col.f32.f16.f16.f32 "
                 "{%0,%1,%2,%3}, {%4,%5,%6,%7}, {%8,%9}, {%0,%1,%2,%3};"
                 : "+f"(d[0]), "+f"(d[1]), "+f"(d[2]), "+f"(d[3])
                 : "r"(a[0]), "r"(a[1]), "r"(a[2]), "r"(a[3]), "r"(b[0]), "r"(b[1]));
}
#define CP16(dst, src) \
    asm volatile("cp.async.cg.shared.global [%0], [%1], 16;" :: "r"(dst), "l"(src))
#define CP_COMMIT() asm volatile("cp.async.commit_group;" ::: "memory")
#define CP_WAIT(n)  asm volatile("cp.async.wait_group %0;" :: "n"(n) : "memory")

__device__ __forceinline__ uint32_t pack_f16x2(float lo, float hi) {
    __half2 h = __floats2half2_rn(lo, hi);   // lo -> low 16, hi -> high 16
    return *(uint32_t*)&h;
}

// ---------------- kernel 1: B' (warp-per-mode, shuffle reduce) ------------
// 64 blocks x 256 thr = 512 warps; warp w handles mode idx = bid*8 + w.
__global__ __launch_bounds__(256) void bp_kernel(
        const float* __restrict__ lam_re, const float* __restrict__ lam_im) {
    int wid = threadIdx.x >> 5, lane = threadIdx.x & 31;
    int idx = blockIdx.x * 8 + wid;
    int j = idx & 63;
    int base = idx & ~63;
    float ljr = lam_re[idx], lji = lam_im[idx];
    float den = ljr * ljr + lji * lji;
    float sr = 0.f, si = 0.f;
    #pragma unroll
    for (int t = 0; t < 2; ++t) {
        int i = lane + 32 * t;
        if (i != j) {
            float lir = lam_re[base + i], lii = lam_im[base + i];
            float rr = (lir * ljr + lii * lji) / den;
            float ri = (lii * ljr - lir * lji) / den;
            float wr = 1.f - rr, wi = -ri;
            sr += 0.5f * logf(wr * wr + wi * wi);
            si += atan2f(wi, wr);
        }
    }
    #pragma unroll
    for (int o = 16; o > 0; o >>= 1) {
        sr += __shfl_xor_sync(0xFFFFFFFFu, sr, o);
        si += __shfl_xor_sync(0xFFFFFFFFu, si, o);
    }
    if (lane == 0) {
        float er = expf(-sr);
        float sn, cs; sincosf(si, &sn, &cs);
        g_Bp[idx] = make_float2(er * cs, -er * sn);
    }
}

// ---------------- kernel 2: fused 3-pass scan + hidden bprep --------------
// blocks 0..127: scan, 128 thr = 4 warps (all 4 SMSPs), TWO (b,k) chains.
// blocks 128..159: bprep (stacked fp16 B operand) on otherwise-idle SMs.
__global__ __launch_bounds__(128) void scan_kernel(
        const float* __restrict__ x,
        const float* __restrict__ lam_re,
        const float* __restrict__ lam_im,
        const float* __restrict__ C_re,
        const float* __restrict__ C_im) {
    int tid = threadIdx.x;

    if (blockIdx.x >= 128) {
        // ---- bprep: B[n][2p] / B[n][2p+1] stacked, x16 scaled fp16 ----
        int base = (blockIdx.x - 128) * 128 + tid;    // 4096 threads
        #pragma unroll 4
        for (int id = base; id < NTOT * 512; id += 4096) {
            int n = id >> 9;
            int p = id & 511;
            int m = n & 63;
            float v0, v1;
            if (n < 64) { v0 = C_re[p * 64 + m]; v1 = -C_im[p * 64 + m]; }
            else        { v0 = C_im[p * 64 + m]; v1 =  C_re[p * 64 + m]; }
            g_Bh[id] = pack_f16x2(v0 * B_SCALE, v1 * B_SCALE);
        }
        return;
    }

    int b = blockIdx.x >> 2;
    int k = ((blockIdx.x & 3) << 1) + (tid >> 6);
    int n = tid & 63;
    int kn = (k << 6) | n;

    float lr = lam_re[kn], li = lam_im[kn];
    float2 Bp = g_Bp[kn];
    float2 s1 = make_float2(0.f, 0.f);
    float2 s2 = make_float2(0.f, 0.f);
    float2 s3 = make_float2(0.f, 0.f);
    float p1r = 0.f, p1i = 0.f, p2r = 0.f, p2i = 0.f, p3r = 0.f, p3i = 0.f;
    float a1c = 1.f, a2c = 1.f;

    __shared__ float xs[128];
    const int xoff = b * K_DIM + k;
    float* xsh = xs + (tid & 64);      // this chain's 64-entry staging slice

    for (int tt = 0; tt < T_DIM; tt += 64) {
        __syncthreads();
        int tl = tt + n;
        xsh[n] = (tl == 0) ? 0.f : x[(tl - 1) * BK + xoff];
        __syncthreads();
        #pragma unroll 8
        for (int j = 0; j < 64; ++j) {
            float xm1 = xsh[j];
            float bxr = Bp.x * xm1, bxi = Bp.y * xm1;
            // state updates use CARRIED p (= lam*s_{t-1}) and alphas
            s3.x = fmaf(a2c, p3r, bxr);  s3.y = fmaf(a2c, p3i, bxi);
            s2.x = fmaf(a1c, p2r, bxr);  s2.y = fmaf(a1c, p2i, bxi);
            s1.x = p1r + bxr;            s1.y = p1i + bxi;
            // prepare next-step products and alphas (off critical path)
            p1r = lr * s1.x - li * s1.y;  p1i = lr * s1.y + li * s1.x;
            p2r = lr * s2.x - li * s2.y;  p2i = lr * s2.y + li * s2.x;
            p3r = lr * s3.x - li * s3.y;  p3i = lr * s3.y + li * s3.x;
            a1c = rsqrtf(1.f + p1r * p1r + p1i * p1i);
            a2c = rsqrtf(1.f + p2r * p2r + p2i * p2i);
            // emit fp16 (scaled by 1/16)
            uint32_t ro = (((tt + j) << 5) + b) * 512 + kn;
            g_Ah[ro] = pack_f16x2(s3.x * A_SCALE, s3.y * A_SCALE);
        }
    }
}

// ---------------- kernel 3: mma.sync f16 GEMM, 4-stage, distance 3 --------
// CTA 512 thr (16 warps, 8m x 2n), tile 256x128, warp tile 32x64.
// Per chunk: CP_WAIT -> __syncthreads -> issue kc+3 -> compute kc.
// Buffer safety: buf(kc+3)%4 == buf(kc-1)%4, consumed before this barrier.
#define SROW 80
#define AH_OFF 0
#define BH_OFF (256 * SROW)               // 20480
#define STAGE_BYTES (BH_OFF + 128 * SROW) // 30720
#define NSTAGE 4
#define NCHUNK 32

extern __shared__ uint8_t dynSmem[];

__device__ __forceinline__ void issue_chunk(int kc, uint32_t sbuf, int rowBase,
                                            int grow, int gc) {
    int k0b = kc * 64;   // byte offset of k32 chunk within a 2048B row
    const uint8_t* gAh = (const uint8_t*)g_Ah;
    const uint8_t* gBh = (const uint8_t*)g_Bh;
    #pragma unroll
    for (int i = 0; i < 2; ++i) {
        int row = grow + i * 128;
        size_t ga = (size_t)(rowBase + row) * (KTOT * 2) + k0b + gc * 16;
        uint32_t so = row * SROW + gc * 16;
        CP16(sbuf + AH_OFF + so, gAh + ga);
    }
    {
        size_t gb = (size_t)grow * (KTOT * 2) + k0b + gc * 16;
        uint32_t so = grow * SROW + gc * 16;
        CP16(sbuf + BH_OFF + so, gBh + gb);
    }
}

__global__ __launch_bounds__(512, 1) void gemm_mma(
        const float* __restrict__ x, const float* __restrict__ D,
        const float* __restrict__ Do, float* __restrict__ out, int writeCplx) {
    __shared__ float Ds[512];
    __shared__ float doSum[64];

    int tid = threadIdx.x;
    int wid = tid >> 5, lane = tid & 31;
    int wm = wid & 7, wn = wid >> 3;          // warp grid 8m x 2n
    int rowBase = blockIdx.x * 256;

    Ds[tid] = D[tid];
    if (tid < 64) {
        float s = 0.f;
        #pragma unroll
        for (int k = 0; k < K_DIM; ++k) s += Do[k * 64 + tid];
        doSum[tid] = s;
    }

    uint32_t sbase0 = smem_u32(dynSmem);

    // ldmatrix per-thread address components
    int mi = lane >> 3;                        // 0..3
    int arow = (lane & 7) + (mi & 1) * 8;
    int acol16 = mi >> 1;
    int bnrow = (mi >> 1) * 8 + (lane & 7);
    int bk16 = mi & 1;

    float acc[2][8][4];
    #pragma unroll
    for (int mt = 0; mt < 2; ++mt)
        #pragma unroll
        for (int nt = 0; nt < 8; ++nt)
            #pragma unroll
            for (int e = 0; e < 4; ++e) acc[mt][nt][e] = 0.f;

    int grow = tid >> 2, gc = tid & 3;         // grow 0..127

    issue_chunk(0, sbase0, rowBase, grow, gc);
    CP_COMMIT();
    issue_chunk(1, sbase0 + STAGE_BYTES, rowBase, grow, gc);
    CP_COMMIT();
    issue_chunk(2, sbase0 + 2 * STAGE_BYTES, rowBase, grow, gc);
    CP_COMMIT();

    int buf = 0;                               // buffer index of chunk kc
    #pragma unroll 1
    for (int kc = 0; kc < NCHUNK; ++kc) {
        if (kc <= NCHUNK - 3)      { CP_WAIT(2); }
        else if (kc == NCHUNK - 2) { CP_WAIT(1); }
        else                       { CP_WAIT(0); }
        __syncthreads();   // all threads: chunk kc landed; compute(kc-1) done
        if (kc + 3 < NCHUNK) {
            int nb = buf + 3; if (nb >= NSTAGE) nb -= NSTAGE;
            issue_chunk(kc + 3, sbase0 + nb * STAGE_BYTES, rowBase, grow, gc);
            CP_COMMIT();
        }

        uint32_t sAh = sbase0 + buf * STAGE_BYTES;
        uint32_t sBh = sAh + BH_OFF;

        #pragma unroll
        for (int ks = 0; ks < 2; ++ks) {
            uint32_t ah[2][4];
            #pragma unroll
            for (int mt = 0; mt < 2; ++mt) {
                uint32_t off = (wm * 32 + mt * 16 + arow) * SROW + ks * 32 + acol16 * 16;
                ldsm_x4(ah[mt], sAh + off);
            }
            #pragma unroll
            for (int ntp = 0; ntp < 4; ++ntp) {
                uint32_t boff = (wn * 64 + ntp * 16 + bnrow) * SROW + ks * 32 + bk16 * 16;
                uint32_t bh4[4];
                ldsm_x4(bh4, sBh + boff);
                #pragma unroll
                for (int mt = 0; mt < 2; ++mt) {
                    mma_f16(acc[mt][2 * ntp],     ah[mt], bh4);
                    mma_f16(acc[mt][2 * ntp + 1], ah[mt], bh4 + 2);
                }
            }
        }
        ++buf; if (buf >= NSTAGE) buf = 0;
    }

    // epilogue (A_SCALE * B_SCALE = 1 -> no extra factor)
    int gID = lane >> 2, tg = lane & 3;
    #pragma unroll
    for (int mt = 0; mt < 2; ++mt) {
        #pragma unroll
        for (int half = 0; half < 2; ++half) {
            int R = rowBase + wm * 32 + mt * 16 + gID + half * 8;
            float xv[K_DIM];
            #pragma unroll
            for (int k = 0; k < K_DIM; ++k) xv[k] = x[R * K_DIM + k];
            #pragma unroll
            for (int nt = 0; nt < 8; ++nt) {
                #pragma unroll
                for (int e = 0; e < 2; ++e) {
                    int col = wn * 64 + nt * 8 + tg * 2 + e;
                    float a = acc[mt][nt][half * 2 + e];
                    if (wn == 0) {  // real part: add x*D + Do, scale by 1/8
                        int m = col;
                        float dt = doSum[m];
                        #pragma unroll
                        for (int k = 0; k < K_DIM; ++k)
                            dt = fmaf(xv[k], Ds[k * 64 + m], dt);
                        float v = (a + dt) * 0.125f;
                        if (writeCplx) out[((size_t)R * 64 + m) * 2] = v;
                        else           out[(size_t)R * 64 + m] = v;
                    } else {        // imag part
                        int m = col - 64;
                        if (writeCplx) out[((size_t)R * 64 + m) * 2 + 1] = a * 0.125f;
                    }
                }
            }
        }
    }
}

// ---------------- launch ----------------
extern "C" void kernel_launch(void* const* d_in, const int* in_sizes, int n_in,
                              void* d_out, int out_size) {
    const float* x = nullptr;
    const float* cbuf[2] = {nullptr, nullptr};
    const float* vbuf[4] = {nullptr, nullptr, nullptr, nullptr};
    int nc = 0, nv = 0;
    for (int i = 0; i < n_in; ++i) {
        int sz = in_sizes[i];
        const float* p = (const float*)d_in[i];
        if (sz == X_SZ) x = p;
        else if (sz == C_SZ) { if (nc < 2) cbuf[nc++] = p; }
        else if (sz == V_SZ) { if (nv < 4) vbuf[nv++] = p; }
    }
    if (!x || nc < 2 || nv < 4) return;
    const float* C_re   = cbuf[0];
    const float* C_im   = cbuf[1];
    const float* lam_re = vbuf[0];
    const float* lam_im = vbuf[1];
    const float* D      = vbuf[2];
    const float* Do     = vbuf[3];

    int writeCplx = (out_size >= 2 * OUT_CPLX) ? 1 : 0;

    cudaFuncSetAttribute(gemm_mma, cudaFuncAttributeMaxDynamicSharedMemorySize,
                         NSTAGE * STAGE_BYTES);

    bp_kernel<<<64, 256>>>(lam_re, lam_im);
    scan_kernel<<<160, 128>>>(x, lam_re, lam_im, C_re, C_im);
    gemm_mma<<<ROWS / 256, 512, NSTAGE * STAGE_BYTES>>>(x, D, Do, (float*)d_out, writeCplx);
}